// round 6
// baseline (speedup 1.0000x reference)
#include <cuda_runtime.h>
#include <cuda_fp16.h>
#include <cstdint>

// Problem constants
#define NQ      16384      // B*H*W
#define NEG     4096       // embeddings per group
#define GR      4
#define KD      64         // embedding dim
#define TQ      128        // queries per block
#define NT      128        // e per tile
#define NTILES  (NEG / NT) // 32
#define CAP     64         // candidate capacity per row

typedef unsigned long long ull;

// ---- device scratch (static, no allocation) ----
__device__ int      g_idx[NQ * GR];               // final argmax indices
__device__ float    g_embn[NEG * GR * KD];        // normalized embedding (fp32)
__device__ int      g_embq[GR * NTILES * 2048];   // int8 swizzled 8KB tile images
__device__ int      g_hist[NEG];                  // histogram of idx[:, 3]
__device__ int      g_cnt[NQ * GR];               // candidate counts
__device__ int      g_cand[NQ * GR * CAP];        // candidate lists

// ============================================================================
// PTX helpers (base-target: ldmatrix sm_75+, mma/cp.async sm_80+)
// ============================================================================
__device__ __forceinline__ uint32_t smem_u32(const void* p) {
    uint32_t a;
    asm("{ .reg .u64 t; cvta.to.shared.u64 t, %1; cvt.u32.u64 %0, t; }"
        : "=r"(a) : "l"(p));
    return a;
}
#define LDSM_X4(r, addr) \
    asm volatile("ldmatrix.sync.aligned.m8n8.x4.shared.b16 {%0,%1,%2,%3}, [%4];" \
        : "=r"((r)[0]), "=r"((r)[1]), "=r"((r)[2]), "=r"((r)[3]) : "r"(addr))

// int8 IMMA: 16x8x32, s32 accumulate (exact)
__device__ __forceinline__ void mma16832_s8(int* c, const uint32_t* a,
                                            const uint32_t* b) {
    asm volatile("mma.sync.aligned.m16n8k32.row.col.s32.s8.s8.s32 "
        "{%0,%1,%2,%3}, {%4,%5,%6,%7}, {%8,%9}, {%0,%1,%2,%3};"
        : "+r"(c[0]), "+r"(c[1]), "+r"(c[2]), "+r"(c[3])
        : "r"(a[0]), "r"(a[1]), "r"(a[2]), "r"(a[3]), "r"(b[0]), "r"(b[1]));
}
__device__ __forceinline__ void cp16(uint32_t dst, const void* src) {
    asm volatile("cp.async.cg.shared.global [%0], [%1], 16;"
                 :: "r"(dst), "l"(src));
}
__device__ __forceinline__ void cp_commit() {
    asm volatile("cp.async.commit_group;" ::: "memory");
}
__device__ __forceinline__ void cp_wait0() {
    asm volatile("cp.async.wait_group 0;" ::: "memory");
}

// macro-row swizzle: rows of 64B, two rows share a 128B line; 16B chunk
// index = ((row&1)*4 + seg) ^ ((row>>1)&7).  Conflict-free for all ldmatrix
// phases (8 rows @ fixed seg -> 8 distinct chunks mod 128B).
__device__ __forceinline__ uint32_t sw_addr(int row, int seg) {
    return (uint32_t)(((row >> 1) * 128) +
                      (((((row & 1) << 2) + seg) ^ ((row >> 1) & 7)) << 4));
}

// ============================================================================
// init: zero counters / histogram
// ============================================================================
__global__ void init_kernel()
{
    int i = blockIdx.x * 256 + threadIdx.x;
    if (i < NQ * GR) g_cnt[i] = 0;
    if (i < NEG)     g_hist[i] = 0;
}

// ============================================================================
// emb prep: normalize rows -> g_embn(fp32); int8 (x126) swizzled tile images.
// One warp per embedding row.
// ============================================================================
__global__ void embprep_kernel(const float* __restrict__ emb)
{
    int warp = (blockIdx.x * blockDim.x + threadIdx.x) >> 5;
    int lane = threadIdx.x & 31;
    if (warp >= NEG * GR) return;
    float2 v = reinterpret_cast<const float2*>(emb + (size_t)warp * KD)[lane];
    float s = v.x * v.x + v.y * v.y;
    #pragma unroll
    for (int m = 16; m >= 1; m >>= 1) s += __shfl_xor_sync(0xffffffffu, s, m);
    float inv = 1.0f / fmaxf(sqrtf(s), 1e-12f);
    float2 o = make_float2(v.x * inv, v.y * inv);
    reinterpret_cast<float2*>(g_embn + (size_t)warp * KD)[lane] = o;

    int q0 = __float2int_rn(o.x * 126.0f);
    int q1 = __float2int_rn(o.y * 126.0f);
    int half = (q0 & 0xFF) | ((q1 & 0xFF) << 8);
    int lo = __shfl_sync(0xffffffffu, half, (lane & 15) * 2);
    int hi = __shfl_sync(0xffffffffu, half, (lane & 15) * 2 + 1);
    if (lane < 16) {
        int w = lane;                       // word w = coords 4w..4w+3
        int word = (lo & 0xFFFF) | (hi << 16);
        int g  = warp >> 12;
        int el = warp & 4095;
        int et = el >> 7, er = el & 127;
        int idx32 = (er >> 1) * 32 +
                    ((((((er & 1) << 2) + (w >> 2)) ^ ((er >> 1) & 7))) << 2) +
                    (w & 3);
        g_embq[(size_t)(g * NTILES + et) * 2048 + idx32] = word;
    }
}

// ============================================================================
// int8 IMMA argmax: m16n8k32 (s32 accum, exact) + int-margin candidate filter.
// z[n,g,c] = z[b*262144 + (g*64+c)*1024 + hw].  Grid (128, 4), 256 thr, 2/SM.
// Dyn smem: [0,512) reduction | A 8KB @512 | B0 @8704 | B1 @16896. Tot 25088.
// ============================================================================
__global__ __launch_bounds__(256, 2)
void vq_mma_kernel(const float* __restrict__ z)
{
    extern __shared__ __align__(1024) char smem[];
    float* sred = reinterpret_cast<float*>(smem);
    uint32_t sbase = smem_u32(smem);
    const uint32_t aA = sbase + 512;
    const uint32_t aB[2] = { sbase + 8704, sbase + 16896 };

    const int tid   = threadIdx.x;
    const int g     = blockIdx.y;
    const int qbase = blockIdx.x * TQ;
    const char* ebase = reinterpret_cast<const char*>(
        g_embq + (size_t)g * NTILES * 2048);

    // ---- preload B(0) via cp.async (32B per thread) ----
    {
        uint32_t d = aB[0] + tid * 16;
        const char* s = ebase + tid * 16;
        cp16(d, s); cp16(d + 4096, s + 4096);
        cp_commit();
    }

    // ---- load z tile to regs, per-CTA absmax, quantize into A ----
    const int q  = tid & 127;
    const int ph = tid >> 7;                 // covers c = ph*32 .. +31
    int marg;
    {
        const int b   = qbase >> 10;
        const int hwb = qbase & 1023;
        const float* zb = z + (size_t)b * 262144 + (size_t)(g * 64) * 1024 + hwb;
        float v[32]; float zm = 0.0f;
        #pragma unroll
        for (int i = 0; i < 32; i++) {
            v[i] = zb[(size_t)(ph * 32 + i) * 1024 + q];
            zm = fmaxf(zm, fabsf(v[i]));
        }
        unsigned um = __reduce_max_sync(0xffffffffu, __float_as_uint(zm));
        if ((tid & 31) == 0) sred[tid >> 5] = __uint_as_float(um);
        __syncthreads();
        if (tid == 0) {
            float m = sred[0];
            #pragma unroll
            for (int i = 1; i < 8; i++) m = fmaxf(m, sred[i]);
            sred[8] = fmaxf(m, 1e-12f);
        }
        __syncthreads();
        const float sz = 126.0f / sred[8];
        marg = (int)(0.25f * sz * 126.0f) + 2;
        int* A32 = reinterpret_cast<int*>(smem + 512);
        #pragma unroll
        for (int w = 0; w < 8; w++) {
            int word = 0;
            #pragma unroll
            for (int j = 0; j < 4; j++) {
                int qv = __float2int_rn(v[w * 4 + j] * sz);
                word |= (qv & 0xFF) << (j * 8);
            }
            int seg = ph * 2 + (w >> 2);
            A32[(q >> 1) * 32 +
                ((((((q & 1) << 2) + seg) ^ ((q >> 1) & 7))) << 2) + (w & 3)] = word;
        }
    }
    cp_wait0();
    __syncthreads();

    const int w8 = tid >> 5;
    const int l  = tid & 31;
    const int qw = (w8 & 3) * 32;
    const int ew = (w8 >> 2) * 64;

    int rm[4], rowg[4];
    #pragma unroll
    for (int qb = 0; qb < 2; qb++)
        #pragma unroll
        for (int h = 0; h < 2; h++) {
            int slot = qb * 2 + h;
            rm[slot]   = (int)0x80000000;
            rowg[slot] = (qbase + qw + qb * 16 + (l >> 2) + h * 8) * GR + g;
        }

    for (int t = 0; t < NTILES; t++) {
        if (t + 1 < NTILES) {
            uint32_t d = aB[(t + 1) & 1] + tid * 16;
            const char* s = ebase + (size_t)(t + 1) * 8192 + tid * 16;
            cp16(d, s); cp16(d + 4096, s + 4096);
            cp_commit();
        }

        int acc[2][8][4];
        #pragma unroll
        for (int qb = 0; qb < 2; qb++)
            #pragma unroll
            for (int eb = 0; eb < 8; eb++)
                #pragma unroll
                for (int j = 0; j < 4; j++) acc[qb][eb][j] = 0;

        const uint32_t base = aB[t & 1];
        #pragma unroll
        for (int ks = 0; ks < 2; ks++) {
            uint32_t RA[2][4];
            #pragma unroll
            for (int qb = 0; qb < 2; qb++) {
                int row = qw + qb * 16 + ((l >> 3) & 1) * 8 + (l & 7);
                int seg = 2 * ks + (l >> 4);
                LDSM_X4(RA[qb], aA + sw_addr(row, seg));
            }
            uint32_t RB[4][4];
            #pragma unroll
            for (int cg = 0; cg < 4; cg++) {
                int er  = ew + cg * 16 + ((l >> 4) & 1) * 8 + (l & 7);
                int seg = 2 * ks + ((l >> 3) & 1);
                LDSM_X4(RB[cg], base + sw_addr(er, seg));
            }
            #pragma unroll
            for (int qb = 0; qb < 2; qb++)
                #pragma unroll
                for (int eb = 0; eb < 8; eb++)
                    mma16832_s8(acc[qb][eb], &RA[qb][0],
                                &RB[eb >> 1][(eb & 1) * 2]);
        }

        // ---- streaming int argmax epilogue ----
        #pragma unroll
        for (int qb = 0; qb < 2; qb++)
            #pragma unroll
            for (int h = 0; h < 2; h++) {
                const int slot = qb * 2 + h;
                int mx = acc[qb][0][h * 2];
                #pragma unroll
                for (int eb = 0; eb < 8; eb++) {
                    mx = max(mx, acc[qb][eb][h * 2]);
                    mx = max(mx, acc[qb][eb][h * 2 + 1]);
                }
                mx = max(mx, __shfl_xor_sync(0xffffffffu, mx, 1));
                mx = max(mx, __shfl_xor_sync(0xffffffffu, mx, 2));
                if (mx > rm[slot]) rm[slot] = mx;
                const int thr = rm[slot] - marg;
                #pragma unroll
                for (int eb = 0; eb < 8; eb++)
                    #pragma unroll
                    for (int j = 0; j < 2; j++) {
                        if (acc[qb][eb][h * 2 + j] >= thr) {
                            int sc = atomicAdd(&g_cnt[rowg[slot]], 1);
                            if (sc < CAP)
                                g_cand[(size_t)rowg[slot] * CAP + sc] =
                                    t * NT + ew + eb * 8 + (l & 3) * 2 + j;
                        }
                    }
            }
        if (t + 1 < NTILES) cp_wait0();
        __syncthreads();
    }
}

// ============================================================================
// Rescore: exact fp32 dot over candidates, first-index tie-break.
// Overflowed rows (cnt > CAP) fall back to an exact full 4096-scan (cold).
// ============================================================================
__global__ __launch_bounds__(256, 4)
void rescore_kernel(const float* __restrict__ z, float* __restrict__ out_idx)
{
    __shared__ float zsh[256 * 9];   // [c][hwi] pad stride 9

    const int tid = threadIdx.x;
    const int n0  = blockIdx.x * 8;
    const int b   = n0 >> 10;
    const int hw0 = n0 & 1023;
    const float* zb = z + (size_t)b * 262144 + hw0;

    #pragma unroll
    for (int w = 0; w < 8; w++) {
        int idx = tid + w * 256;
        int c = idx >> 3, hwi = idx & 7;
        zsh[c * 9 + hwi] = zb[(size_t)c * 1024 + hwi];
    }
    __syncthreads();

    const int wid = tid >> 5, lane = tid & 31;
    for (int rr = 0; rr < 4; rr++) {
        int lr  = wid * 4 + rr;
        int hwi = lr >> 2;
        int g   = lr & 3;
        int n   = n0 + hwi;
        int row = n * GR + g;
        int cnt = g_cnt[row];
        const float* zr = zsh + (g * 64) * 9 + hwi;

        float bv = -3.0e38f;
        int   be = 0x7FFFFFFF;
        if (cnt > CAP) {
            for (int e = lane; e < NEG; e += 32) {
                const float4* er = reinterpret_cast<const float4*>(
                    g_embn + ((size_t)(g * NEG + e)) * KD);
                float acc = 0.0f;
                #pragma unroll
                for (int kk = 0; kk < 16; kk++) {
                    float4 ev = er[kk];
                    acc = fmaf(zr[(kk * 4 + 0) * 9], ev.x, acc);
                    acc = fmaf(zr[(kk * 4 + 1) * 9], ev.y, acc);
                    acc = fmaf(zr[(kk * 4 + 2) * 9], ev.z, acc);
                    acc = fmaf(zr[(kk * 4 + 3) * 9], ev.w, acc);
                }
                if (acc > bv || (acc == bv && e < be)) { bv = acc; be = e; }
            }
        } else {
            for (int base = 0; base < cnt; base += 32) {
                int c = base + lane;
                if (c < cnt) {
                    int e = g_cand[(size_t)row * CAP + c];
                    const float4* er = reinterpret_cast<const float4*>(
                        g_embn + ((size_t)(g * NEG + e)) * KD);
                    float acc = 0.0f;
                    #pragma unroll
                    for (int kk = 0; kk < 16; kk++) {
                        float4 ev = er[kk];
                        acc = fmaf(zr[(kk * 4 + 0) * 9], ev.x, acc);
                        acc = fmaf(zr[(kk * 4 + 1) * 9], ev.y, acc);
                        acc = fmaf(zr[(kk * 4 + 2) * 9], ev.z, acc);
                        acc = fmaf(zr[(kk * 4 + 3) * 9], ev.w, acc);
                    }
                    if (acc > bv || (acc == bv && e < be)) { bv = acc; be = e; }
                }
            }
        }
        unsigned u = __float_as_uint(bv);
        u = ((int)u < 0) ? ~u : (u | 0x80000000u);
        unsigned m = __reduce_max_sync(0xffffffffu, u);
        unsigned bidm = (u == m) ? (unsigned)be : 0xFFFFFFFFu;
        unsigned bi = __reduce_min_sync(0xffffffffu, bidm);
        if (lane == 0) {
            g_idx[row] = (int)bi;
            out_idx[row] = (float)bi;
        }
    }
}

// ============================================================================
// quant: out[b, g*64+c, h, w] = embn[g*4096 + idx[n,g], c]
// ============================================================================
__global__ void quant_kernel(float* __restrict__ out)
{
    int o = blockIdx.x * blockDim.x + threadIdx.x;
    if (o >= 16 * 256 * 1024) return;
    int hw = o & 1023;
    int ch = (o >> 10) & 255;
    int b  = o >> 18;
    int gg = ch >> 6, c = ch & 63;
    int n  = (b << 10) + hw;
    int v  = g_idx[n * GR + gg];
    out[o] = g_embn[((size_t)((gg << 12) + v)) * KD + c];
}

// one-hot of idx[:, 3] + histogram
__global__ void scatter_kernel(float* __restrict__ out_me)
{
    int n = blockIdx.x * blockDim.x + threadIdx.x;
    if (n >= NQ) return;
    int v = g_idx[n * GR + 3];
    out_me[(size_t)n * NEG + v] = 1.0f;
    atomicAdd(&g_hist[v], 1);
}

__global__ void perp_kernel(float* __restrict__ out_p)
{
    __shared__ float red[32];
    int t = threadIdx.x;
    float s = 0.0f;
    for (int i = t; i < NEG; i += 1024) {
        float p = (float)g_hist[i] * (1.0f / 16384.0f);
        s += p * logf(p + 1e-10f);
    }
    #pragma unroll
    for (int m = 16; m >= 1; m >>= 1) s += __shfl_xor_sync(0xffffffffu, s, m);
    if ((t & 31) == 0) red[t >> 5] = s;
    __syncthreads();
    if (t < 32) {
        float x = red[t];
        #pragma unroll
        for (int m = 16; m >= 1; m >>= 1) x += __shfl_xor_sync(0xffffffffu, x, m);
        if (t == 0) out_p[0] = expf(-x);
    }
}

// ============================================================================
// Output layout (fp32, concatenated, 71,368,717 elements):
//   [0, 4194304)            quant
//   [4194304, +12)          vq_loss(4) commit_loss(4) codebook_usage(4) = zeros
//   [4194316]               perplexity
//   [4194317, +16384*4096)  min_encodings
//   [71303181, +65536)      idx (cast to float)
// ============================================================================
extern "C" void kernel_launch(void* const* d_in, const int* in_sizes, int n_in,
                              void* d_out, int out_size)
{
    const float* z   = (const float*)d_in[0];
    const float* emb = (const float*)d_in[1];
    float* out = (float*)d_out;

    const size_t QUANT   = (size_t)16 * 256 * 1024;          // 4194304
    const size_t PERP    = QUANT + 12;
    const size_t ME_OFF  = QUANT + 13;
    const size_t ME_SZ   = (size_t)NQ * NEG;                  // 67108864
    const size_t IDX_OFF = ME_OFF + ME_SZ;                    // 71303181

    const int SMEM = 25088;   // red 512 + A 8KB + 2x8KB B
    cudaFuncSetAttribute(vq_mma_kernel,
                         cudaFuncAttributeMaxDynamicSharedMemorySize, SMEM);

    // zero losses + perplexity slot + min_encodings (268 MB)
    cudaMemsetAsync(out + QUANT, 0, (13 + ME_SZ) * sizeof(float));

    init_kernel<<<256, 256>>>();
    embprep_kernel<<<2048, 256>>>(emb);

    dim3 agrid(NQ / TQ, GR);   // (128, 4)
    vq_mma_kernel<<<agrid, 256, SMEM>>>(z);

    rescore_kernel<<<NQ / 8, 256>>>(z, out + IDX_OFF);

    quant_kernel<<<16384, 256>>>(out);
    scatter_kernel<<<64, 256>>>(out + ME_OFF);
    perp_kernel<<<1, 1024>>>(out + PERP);
}

// round 7
// speedup vs baseline: 1.2439x; 1.2439x over previous
#include <cuda_runtime.h>
#include <cuda_fp16.h>
#include <cstdint>

// Problem constants
#define NQ      16384      // B*H*W
#define NEG     4096       // embeddings per group
#define GR      4
#define KD      64         // embedding dim
#define TQ      128        // queries per block
#define NT      128        // e per tile
#define NTILES  32         // tiles per group
#define TPI     8          // tiles per item (e-quarter)
#define NITEMS  2048       // 128 qtiles * 4 groups * 4 e-quarters
#define CAP     64         // candidate capacity per row

#define QUANT_SZ 4194304ULL
#define ME_OFFC  4194317ULL   // QUANT_SZ + 13 (odd -> unaligned head)

typedef unsigned long long ull;

// ---- device scratch (static, no allocation) ----
__device__ int      g_idx[NQ * GR];               // final argmax indices
__device__ float    g_embn[NEG * GR * KD];        // normalized embedding (fp32)
__device__ int      g_embh[GR * NTILES * 4096];   // fp16 swizzled 16KB tile images
__device__ int      g_hist[NEG];                  // histogram of idx[:, 3]
__device__ int      g_cnt[NQ * GR];               // candidate counts
__device__ int      g_cand[NQ * GR * CAP];        // packed (sortkey16|idx16)

// ============================================================================
// PTX helpers (base-target: ldmatrix sm_75+, mma.sync sm_80+)
// ============================================================================
__device__ __forceinline__ uint32_t smem_u32(const void* p) {
    uint32_t a;
    asm("{ .reg .u64 t; cvta.to.shared.u64 t, %1; cvt.u32.u64 %0, t; }"
        : "=r"(a) : "l"(p));
    return a;
}
#define LDSM_X4(r, addr) \
    asm volatile("ldmatrix.sync.aligned.m8n8.x4.shared.b16 {%0,%1,%2,%3}, [%4];" \
        : "=r"((r)[0]), "=r"((r)[1]), "=r"((r)[2]), "=r"((r)[3]) : "r"(addr))

__device__ __forceinline__ void mma16816(float* c, const uint32_t* a,
                                         const uint32_t* b) {
    asm volatile("mma.sync.aligned.m16n8k16.row.col.f32.f16.f16.f32 "
        "{%0,%1,%2,%3}, {%4,%5,%6,%7}, {%8,%9}, {%0,%1,%2,%3};"
        : "+f"(c[0]), "+f"(c[1]), "+f"(c[2]), "+f"(c[3])
        : "r"(a[0]), "r"(a[1]), "r"(a[2]), "r"(a[3]), "r"(b[0]), "r"(b[1]));
}

// fp16 bits <-> monotone sortable u16 key
__device__ __forceinline__ unsigned f2key(float v) {
    unsigned h = (unsigned)__half_as_ushort(__float2half_rn(v));
    return h ^ ((h & 0x8000u) ? 0xFFFFu : 0x8000u);
}
__device__ __forceinline__ float key2f(unsigned k) {
    unsigned h = (k & 0x8000u) ? (k ^ 0x8000u) : (~k & 0xFFFFu);
    return __half2float(__ushort_as_half((unsigned short)h));
}

// ============================================================================
// init: zero counters / histogram
// ============================================================================
__global__ void init_kernel()
{
    int i = blockIdx.x * 256 + threadIdx.x;
    if (i < NQ * GR) g_cnt[i] = 0;
    if (i < NEG)     g_hist[i] = 0;
}

// ============================================================================
// emb prep: normalize rows -> g_embn(fp32); fp16 XOR-swizzled tile images.
// (validated in R4)  One warp per embedding row.
// ============================================================================
__global__ void embprep_kernel(const float* __restrict__ emb)
{
    int warp = (blockIdx.x * blockDim.x + threadIdx.x) >> 5;
    int lane = threadIdx.x & 31;
    if (warp >= NEG * GR) return;
    float2 v = reinterpret_cast<const float2*>(emb + (size_t)warp * KD)[lane];
    float s = v.x * v.x + v.y * v.y;
    #pragma unroll
    for (int m = 16; m >= 1; m >>= 1) s += __shfl_xor_sync(0xffffffffu, s, m);
    float inv = 1.0f / fmaxf(sqrtf(s), 1e-12f);
    float2 o = make_float2(v.x * inv, v.y * inv);
    reinterpret_cast<float2*>(g_embn + (size_t)warp * KD)[lane] = o;

    __half2 h2 = __floats2half2_rn(o.x, o.y);
    int w; memcpy(&w, &h2, 4);
    int g  = warp >> 12;
    int el = warp & 4095;
    int et = el >> 7, er = el & 127;
    int ui = er * 32 + ((((lane >> 2)) ^ (er & 7)) << 2) + (lane & 3);
    g_embh[(size_t)(g * NTILES + et) * 4096 + ui] = w;
}

// ============================================================================
// Tensor-core argmax via mma.sync m16n8k16 (fp16 in, fp32 accum), R4 core.
// Item = (qtile, group, e-quarter): grid 2048, 256 thr, 2 CTAs/SM, 7 waves.
// Also streams zero-stores covering its 32768-float min_encodings slice.
// Dyn smem: [0,512) margins | A 16KB @1024 | B0 @17408 | B1 @33792.
// ============================================================================
__global__ __launch_bounds__(256, 2)
void vq_mma_kernel(const float* __restrict__ z, float* __restrict__ out)
{
    extern __shared__ __align__(1024) char smem[];
    float* smarg = reinterpret_cast<float*>(smem);
    uint32_t sbase = smem_u32(smem);
    const uint32_t aA = sbase + 1024;
    const uint32_t aB[2] = { sbase + 17408, sbase + 33792 };
    int4* sB4[2] = { reinterpret_cast<int4*>(smem + 17408),
                     reinterpret_cast<int4*>(smem + 33792) };

    const int tid   = threadIdx.x;
    const int item  = blockIdx.x;
    const int eq    = item & 3;
    const int g     = (item >> 2) & 3;
    const int qbase = (item >> 4) * TQ;

    // min_encodings zero-slice pointers for this CTA
    const size_t S = ME_OFFC + (size_t)item * 32768;
    float4* me4 = reinterpret_cast<float4*>(out + S + 3);   // 16B aligned

    // ---- build A tile (fp16, swizzled) + per-row margin ----
    {
        const int b   = qbase >> 10;
        const int hwb = qbase & 1023;
        const float* zb = z + (size_t)b * 262144 + (size_t)(g * 64) * 1024 + hwb;
        const int q  = tid & 127;
        const int ph = tid >> 7;                 // handles c-pairs ph*16..+15
        __half2* A2 = reinterpret_cast<__half2*>(smem + 1024);
        float n2 = 0.0f;
        #pragma unroll
        for (int i = 0; i < 16; i++) {
            int c = (ph * 16 + i) * 2;
            float v0 = zb[(size_t)c * 1024 + q];
            float v1 = zb[(size_t)(c + 1) * 1024 + q];
            n2 += v0 * v0 + v1 * v1;
            int ui = q * 32 + (((c >> 3) ^ (q & 7)) << 2) + ((c & 7) >> 1);
            A2[ui] = __floats2half2_rn(v0, v1);
        }
        if (ph == 0) smarg[q] = n2;
        // ---- preload B(first tile of this quarter) ----
        {
            const int4* s4 = reinterpret_cast<const int4*>(
                g_embh + (size_t)(g * NTILES + eq * TPI) * 4096);
            #pragma unroll
            for (int i = 0; i < 4; i++) sB4[0][tid + i * 256] = s4[tid + i * 256];
        }
        __syncthreads();
        if (ph == 1) smarg[q] = 0.008f * sqrtf(smarg[q] + n2);
        __syncthreads();
    }

    const int w  = tid >> 5;
    const int l  = tid & 31;
    const int qw = (w & 3) * 32;
    const int ew = (w >> 2) * 64;

    float rm[4], marg[4];
    int   rowg[4];
    #pragma unroll
    for (int qb = 0; qb < 2; qb++)
        #pragma unroll
        for (int h = 0; h < 2; h++) {
            int slot = qb * 2 + h;
            int rq = qw + qb * 16 + (l >> 2) + h * 8;
            rm[slot]   = -3.0e38f;
            marg[slot] = smarg[rq];
            rowg[slot] = (qbase + rq) * GR + g;
        }

    const int4* esrc = reinterpret_cast<const int4*>(
        g_embh + (size_t)(g * NTILES + eq * TPI) * 4096);

    for (int tt = 0; tt < TPI; tt++) {
        // prefetch next B tile into the other buffer
        if (tt + 1 < TPI) {
            const int4* s4 = esrc + (size_t)(tt + 1) * 1024;
            int4* d4 = sB4[(tt + 1) & 1];
            #pragma unroll
            for (int i = 0; i < 4; i++) d4[tid + i * 256] = s4[tid + i * 256];
        }

        // ---- streamed zero-stores for min_encodings slice ----
        {
            const float4 z4 = make_float4(0.f, 0.f, 0.f, 0.f);
            #pragma unroll
            for (int i = 0; i < 4; i++) {
                int j = tt * 1024 + i * 256 + tid;
                if (j < 8191) me4[j] = z4;
            }
            if (tt == 0) {
                if (tid < 3)  out[S + tid] = 0.0f;        // unaligned head
                if (tid == 3) out[S + 32767] = 0.0f;      // tail float
            }
        }

        float acc[2][8][4];
        #pragma unroll
        for (int qb = 0; qb < 2; qb++)
            #pragma unroll
            for (int eb = 0; eb < 8; eb++)
                #pragma unroll
                for (int j = 0; j < 4; j++) acc[qb][eb][j] = 0.0f;

        const uint32_t base = aB[tt & 1];
        #pragma unroll
        for (int ks = 0; ks < 4; ks++) {
            uint32_t RA[2][4];
            #pragma unroll
            for (int qb = 0; qb < 2; qb++) {
                int row = qw + qb * 16 + (l & 15);
                int blk = ks * 2 + (l >> 4);
                LDSM_X4(RA[qb], aA + row * 128 + ((blk ^ (row & 7)) << 4));
            }
            uint32_t RB[4][4];
            #pragma unroll
            for (int ebp = 0; ebp < 4; ebp++) {
                int row = ew + ebp * 16 + (l & 7) + ((l >> 4) << 3);
                int blk = ks * 2 + ((l >> 3) & 1);
                LDSM_X4(RB[ebp], base + row * 128 + ((blk ^ (row & 7)) << 4));
            }
            #pragma unroll
            for (int qb = 0; qb < 2; qb++)
                #pragma unroll
                for (int eb = 0; eb < 8; eb++)
                    mma16816(acc[qb][eb], RA[qb], &RB[eb >> 1][(eb & 1) * 2]);
        }

        // ---- streaming argmax epilogue, packed (sortkey|idx) push ----
        const int tg = eq * TPI + tt;   // global tile index
        #pragma unroll
        for (int qb = 0; qb < 2; qb++)
            #pragma unroll
            for (int h = 0; h < 2; h++) {
                const int slot = qb * 2 + h;
                float mx = -3.0e38f;
                #pragma unroll
                for (int eb = 0; eb < 8; eb++) {
                    mx = fmaxf(mx, acc[qb][eb][h * 2]);
                    mx = fmaxf(mx, acc[qb][eb][h * 2 + 1]);
                }
                mx = fmaxf(mx, __shfl_xor_sync(0xffffffffu, mx, 1));
                mx = fmaxf(mx, __shfl_xor_sync(0xffffffffu, mx, 2));
                if (mx > rm[slot]) rm[slot] = mx;
                const float thr = rm[slot] - marg[slot];
                #pragma unroll
                for (int eb = 0; eb < 8; eb++) {
                    #pragma unroll
                    for (int j = 0; j < 2; j++) {
                        float vv = acc[qb][eb][h * 2 + j];
                        if (vv >= thr) {
                            int sc = atomicAdd(&g_cnt[rowg[slot]], 1);
                            if (sc < CAP) {
                                unsigned e = (unsigned)(tg * NT + ew + eb * 8 +
                                                        (l & 3) * 2 + j);
                                g_cand[(size_t)rowg[slot] * CAP + sc] =
                                    (int)((f2key(vv) << 16) | e);
                            }
                        }
                    }
                }
            }
        __syncthreads();
    }
}

// ============================================================================
// Rescore: stored-fp16-score prune, then exact fp32 dot on the survivors
// (first-index tie-break).  Overflowed rows -> exact full 4096-scan.
// ============================================================================
__global__ __launch_bounds__(256, 4)
void rescore_kernel(const float* __restrict__ z, float* __restrict__ out_idx)
{
    __shared__ float zsh[256 * 9];   // [c][hwi] pad stride 9

    const int tid = threadIdx.x;
    const int n0  = blockIdx.x * 8;
    const int b   = n0 >> 10;
    const int hw0 = n0 & 1023;
    const float* zb = z + (size_t)b * 262144 + hw0;

    #pragma unroll
    for (int w = 0; w < 8; w++) {
        int idx = tid + w * 256;
        int c = idx >> 3, hwi = idx & 7;
        zsh[c * 9 + hwi] = zb[(size_t)c * 1024 + hwi];
    }
    __syncthreads();

    const int wid = tid >> 5, lane = tid & 31;
    for (int rr = 0; rr < 4; rr++) {
        int lr  = wid * 4 + rr;
        int hwi = lr >> 2;
        int g   = lr & 3;
        int n   = n0 + hwi;
        int row = n * GR + g;
        int cnt = g_cnt[row];
        const float* zr = zsh + (g * 64) * 9 + hwi;

        float bv = -3.0e38f;
        int   be = 0x7FFFFFFF;
        if (cnt > CAP) {
            // overflow: exact scan of all 4096 embeddings (cold path)
            for (int e = lane; e < NEG; e += 32) {
                const float4* er = reinterpret_cast<const float4*>(
                    g_embn + ((size_t)(g * NEG + e)) * KD);
                float acc = 0.0f;
                #pragma unroll
                for (int kk = 0; kk < 16; kk++) {
                    float4 ev = er[kk];
                    acc = fmaf(zr[(kk * 4 + 0) * 9], ev.x, acc);
                    acc = fmaf(zr[(kk * 4 + 1) * 9], ev.y, acc);
                    acc = fmaf(zr[(kk * 4 + 2) * 9], ev.z, acc);
                    acc = fmaf(zr[(kk * 4 + 3) * 9], ev.w, acc);
                }
                if (acc > bv || (acc == bv && e < be)) { bv = acc; be = e; }
            }
        } else {
            // row norm (for prune margin)
            float s2 = 0.0f;
            #pragma unroll
            for (int c2 = 0; c2 < 2; c2++) {
                float vv = zr[(lane + c2 * 32) * 9];
                s2 += vv * vv;
            }
            #pragma unroll
            for (int m = 16; m >= 1; m >>= 1)
                s2 += __shfl_xor_sync(0xffffffffu, s2, m);

            int p0 = (lane < cnt)      ? g_cand[(size_t)row * CAP + lane]      : 0;
            int p1 = (lane + 32 < cnt) ? g_cand[(size_t)row * CAP + lane + 32] : 0;
            unsigned k0 = (unsigned)p0 >> 16;
            unsigned k1 = (unsigned)p1 >> 16;
            unsigned mk = __reduce_max_sync(0xffffffffu, max(k0, k1));
            float thr = key2f(mk) - 0.0065f * sqrtf(s2);

            #pragma unroll
            for (int hf = 0; hf < 2; hf++) {
                int p = hf ? p1 : p0;
                bool valid = hf ? (lane + 32 < cnt) : (lane < cnt);
                if (valid && key2f((unsigned)p >> 16) >= thr) {
                    int e = p & 0xFFFF;
                    const float4* er = reinterpret_cast<const float4*>(
                        g_embn + ((size_t)(g * NEG + e)) * KD);
                    float acc = 0.0f;
                    #pragma unroll
                    for (int kk = 0; kk < 16; kk++) {
                        float4 ev = er[kk];
                        acc = fmaf(zr[(kk * 4 + 0) * 9], ev.x, acc);
                        acc = fmaf(zr[(kk * 4 + 1) * 9], ev.y, acc);
                        acc = fmaf(zr[(kk * 4 + 2) * 9], ev.z, acc);
                        acc = fmaf(zr[(kk * 4 + 3) * 9], ev.w, acc);
                    }
                    if (acc > bv || (acc == bv && e < be)) { bv = acc; be = e; }
                }
            }
        }
        unsigned u = __float_as_uint(bv);
        u = ((int)u < 0) ? ~u : (u | 0x80000000u);
        unsigned m = __reduce_max_sync(0xffffffffu, u);
        unsigned bidm = (u == m) ? (unsigned)be : 0xFFFFFFFFu;
        unsigned bi = __reduce_min_sync(0xffffffffu, bidm);
        if (lane == 0) {
            g_idx[row] = (int)bi;
            out_idx[row] = (float)bi;
        }
    }
}

// ============================================================================
// quant: out[b, g*64+c, h, w] = embn[g*4096 + idx[n,g], c]
// ============================================================================
__global__ void quant_kernel(float* __restrict__ out)
{
    int o = blockIdx.x * blockDim.x + threadIdx.x;
    if (o >= 16 * 256 * 1024) return;
    int hw = o & 1023;
    int ch = (o >> 10) & 255;
    int b  = o >> 18;
    int gg = ch >> 6, c = ch & 63;
    int n  = (b << 10) + hw;
    int v  = g_idx[n * GR + gg];
    out[o] = g_embn[((size_t)((gg << 12) + v)) * KD + c];
}

// one-hot of idx[:, 3] + histogram
__global__ void scatter_kernel(float* __restrict__ out_me)
{
    int n = blockIdx.x * blockDim.x + threadIdx.x;
    if (n >= NQ) return;
    int v = g_idx[n * GR + 3];
    out_me[(size_t)n * NEG + v] = 1.0f;
    atomicAdd(&g_hist[v], 1);
}

__global__ void perp_kernel(float* __restrict__ out_p)
{
    __shared__ float red[32];
    int t = threadIdx.x;
    float s = 0.0f;
    for (int i = t; i < NEG; i += 1024) {
        float p = (float)g_hist[i] * (1.0f / 16384.0f);
        s += p * logf(p + 1e-10f);
    }
    #pragma unroll
    for (int m = 16; m >= 1; m >>= 1) s += __shfl_xor_sync(0xffffffffu, s, m);
    if ((t & 31) == 0) red[t >> 5] = s;
    __syncthreads();
    if (t < 32) {
        float x = red[t];
        #pragma unroll
        for (int m = 16; m >= 1; m >>= 1) x += __shfl_xor_sync(0xffffffffu, x, m);
        if (t == 0) out_p[0] = expf(-x);
    }
}

// ============================================================================
// Output layout (fp32, concatenated, 71,368,717 elements):
//   [0, 4194304)            quant
//   [4194304, +12)          vq_loss(4) commit_loss(4) codebook_usage(4) = zeros
//   [4194316]               perplexity
//   [4194317, +16384*4096)  min_encodings (zeroed inside vq_mma_kernel)
//   [71303181, +65536)      idx (cast to float)
// ============================================================================
extern "C" void kernel_launch(void* const* d_in, const int* in_sizes, int n_in,
                              void* d_out, int out_size)
{
    const float* z   = (const float*)d_in[0];
    const float* emb = (const float*)d_in[1];
    float* out = (float*)d_out;

    const size_t QUANT   = QUANT_SZ;                          // 4194304
    const size_t PERP    = QUANT + 12;
    const size_t ME_OFF  = ME_OFFC;                           // 4194317
    const size_t ME_SZ   = (size_t)NQ * NEG;                  // 67108864
    const size_t IDX_OFF = ME_OFF + ME_SZ;                    // 71303181

    const int SMEM = 50176;   // margins + A 16KB + 2x16KB B
    cudaFuncSetAttribute(vq_mma_kernel,
                         cudaFuncAttributeMaxDynamicSharedMemorySize, SMEM);

    // only losses + perplexity slot (13 floats); min_encodings zeroed in-kernel
    cudaMemsetAsync(out + QUANT, 0, 13 * sizeof(float));

    init_kernel<<<256, 256>>>();
    embprep_kernel<<<2048, 256>>>(emb);

    vq_mma_kernel<<<NITEMS, 256, SMEM>>>(z, out);

    rescore_kernel<<<NQ / 8, 256>>>(z, out + IDX_OFF);

    quant_kernel<<<16384, 256>>>(out);
    scatter_kernel<<<64, 256>>>(out + ME_OFF);
    perp_kernel<<<1, 1024>>>(out + PERP);
}

// round 8
// speedup vs baseline: 1.4924x; 1.1997x over previous
#include <cuda_runtime.h>
#include <cuda_fp16.h>
#include <cstdint>

// Problem constants
#define NQ      16384      // B*H*W
#define NEG     4096       // embeddings per group
#define GR      4
#define KD      64         // embedding dim
#define TQ      128        // queries per block
#define NT      128        // e per tile
#define NTILES  32         // tiles per group
#define NITEMS  512        // 128 qtiles * 4 groups
#define CAP     64         // candidate capacity per row

#define QUANT_SZ 4194304ULL
#define ME_OFFC  4194317ULL   // QUANT_SZ + 13 (odd -> unaligned head)

typedef unsigned long long ull;

// ---- device scratch (static, no allocation) ----
__device__ int      g_idx[NQ * GR];               // final argmax indices
__device__ float    g_embn[NEG * GR * KD];        // normalized embedding (fp32)
__device__ int      g_embh[GR * NTILES * 4096];   // fp16 swizzled 16KB tile images
__device__ int      g_hist[NEG];                  // histogram of idx[:, 3]
__device__ int      g_cnt[NQ * GR];               // candidate counts
__device__ int      g_cand[NQ * GR * CAP];        // packed (sortkey16|idx16)

// ============================================================================
// PTX helpers (base-target: ldmatrix sm_75+, mma.sync sm_80+)
// ============================================================================
__device__ __forceinline__ uint32_t smem_u32(const void* p) {
    uint32_t a;
    asm("{ .reg .u64 t; cvta.to.shared.u64 t, %1; cvt.u32.u64 %0, t; }"
        : "=r"(a) : "l"(p));
    return a;
}
#define LDSM_X4(r, addr) \
    asm volatile("ldmatrix.sync.aligned.m8n8.x4.shared.b16 {%0,%1,%2,%3}, [%4];" \
        : "=r"((r)[0]), "=r"((r)[1]), "=r"((r)[2]), "=r"((r)[3]) : "r"(addr))

__device__ __forceinline__ void mma16816(float* c, const uint32_t* a,
                                         const uint32_t* b) {
    asm volatile("mma.sync.aligned.m16n8k16.row.col.f32.f16.f16.f32 "
        "{%0,%1,%2,%3}, {%4,%5,%6,%7}, {%8,%9}, {%0,%1,%2,%3};"
        : "+f"(c[0]), "+f"(c[1]), "+f"(c[2]), "+f"(c[3])
        : "r"(a[0]), "r"(a[1]), "r"(a[2]), "r"(a[3]), "r"(b[0]), "r"(b[1]));
}

// fp16 bits <-> monotone sortable u16 key
__device__ __forceinline__ unsigned f2key(float v) {
    unsigned h = (unsigned)__half_as_ushort(__float2half_rn(v));
    return h ^ ((h & 0x8000u) ? 0xFFFFu : 0x8000u);
}
__device__ __forceinline__ float key2f(unsigned k) {
    unsigned h = (k & 0x8000u) ? (k ^ 0x8000u) : (~k & 0xFFFFu);
    return __half2float(__ushort_as_half((unsigned short)h));
}

// ============================================================================
// init: zero counters / histogram
// ============================================================================
__global__ void init_kernel()
{
    int i = blockIdx.x * 256 + threadIdx.x;
    if (i < NQ * GR) g_cnt[i] = 0;
    if (i < NEG)     g_hist[i] = 0;
}

// ============================================================================
// emb prep: normalize rows -> g_embn(fp32); fp16 XOR-swizzled tile images.
// (validated in R4)  One warp per embedding row.
// ============================================================================
__global__ void embprep_kernel(const float* __restrict__ emb)
{
    int warp = (blockIdx.x * blockDim.x + threadIdx.x) >> 5;
    int lane = threadIdx.x & 31;
    if (warp >= NEG * GR) return;
    float2 v = reinterpret_cast<const float2*>(emb + (size_t)warp * KD)[lane];
    float s = v.x * v.x + v.y * v.y;
    #pragma unroll
    for (int m = 16; m >= 1; m >>= 1) s += __shfl_xor_sync(0xffffffffu, s, m);
    float inv = 1.0f / fmaxf(sqrtf(s), 1e-12f);
    float2 o = make_float2(v.x * inv, v.y * inv);
    reinterpret_cast<float2*>(g_embn + (size_t)warp * KD)[lane] = o;

    __half2 h2 = __floats2half2_rn(o.x, o.y);
    int w; memcpy(&w, &h2, 4);
    int g  = warp >> 12;
    int el = warp & 4095;
    int et = el >> 7, er = el & 127;
    int ui = er * 32 + ((((lane >> 2)) ^ (er & 7)) << 2) + (lane & 3);
    g_embh[(size_t)(g * NTILES + et) * 4096 + ui] = w;
}

// ============================================================================
// Tensor-core argmax via mma.sync m16n8k16 (fp16 in, fp32 accum), R4 core.
// Item = (qtile, group): grid 512, 256 thr, 2 CTAs/SM.
// Streams zero-stores covering its 131072-float min_encodings slice.
// Epilogue: half2 SIMD max tree + gated compare scan (rare).
// Dyn smem: [0,512) margins | A 16KB @1024 | B0 @17408 | B1 @33792.
// ============================================================================
__global__ __launch_bounds__(256, 2)
void vq_mma_kernel(const float* __restrict__ z, float* __restrict__ out)
{
    extern __shared__ __align__(1024) char smem[];
    float* smarg = reinterpret_cast<float*>(smem);
    uint32_t sbase = smem_u32(smem);
    const uint32_t aA = sbase + 1024;
    const uint32_t aB[2] = { sbase + 17408, sbase + 33792 };
    int4* sB4[2] = { reinterpret_cast<int4*>(smem + 17408),
                     reinterpret_cast<int4*>(smem + 33792) };

    const int tid   = threadIdx.x;
    const int item  = blockIdx.x;
    const int g     = item & 3;
    const int qbase = (item >> 2) * TQ;

    // min_encodings zero-slice for this CTA: 131072 floats
    const size_t S = ME_OFFC + (size_t)item * 131072;
    float4* me4 = reinterpret_cast<float4*>(out + S + 3);   // 16B aligned

    // ---- build A tile (fp16, swizzled) + per-row margin ----
    {
        const int b   = qbase >> 10;
        const int hwb = qbase & 1023;
        const float* zb = z + (size_t)b * 262144 + (size_t)(g * 64) * 1024 + hwb;
        const int q  = tid & 127;
        const int ph = tid >> 7;                 // handles c-pairs ph*16..+15
        __half2* A2 = reinterpret_cast<__half2*>(smem + 1024);
        float n2 = 0.0f;
        #pragma unroll
        for (int i = 0; i < 16; i++) {
            int c = (ph * 16 + i) * 2;
            float v0 = zb[(size_t)c * 1024 + q];
            float v1 = zb[(size_t)(c + 1) * 1024 + q];
            n2 += v0 * v0 + v1 * v1;
            int ui = q * 32 + (((c >> 3) ^ (q & 7)) << 2) + ((c & 7) >> 1);
            A2[ui] = __floats2half2_rn(v0, v1);
        }
        if (ph == 0) smarg[q] = n2;
        // ---- preload B(0) ----
        {
            const int4* s4 = reinterpret_cast<const int4*>(
                g_embh + (size_t)(g * NTILES) * 4096);
            #pragma unroll
            for (int i = 0; i < 4; i++) sB4[0][tid + i * 256] = s4[tid + i * 256];
        }
        __syncthreads();
        if (ph == 1) smarg[q] = 0.006f * sqrtf(smarg[q] + n2);
        __syncthreads();
    }

    const int w  = tid >> 5;
    const int l  = tid & 31;
    const int qw = (w & 3) * 32;
    const int ew = (w >> 2) * 64;

    float rm[4], marg[4];
    int   rowg[4];
    #pragma unroll
    for (int qb = 0; qb < 2; qb++)
        #pragma unroll
        for (int h = 0; h < 2; h++) {
            int slot = qb * 2 + h;
            int rq = qw + qb * 16 + (l >> 2) + h * 8;
            rm[slot]   = -3.0e38f;
            marg[slot] = smarg[rq];
            rowg[slot] = (qbase + rq) * GR + g;
        }

    const int4* esrc = reinterpret_cast<const int4*>(
        g_embh + (size_t)(g * NTILES) * 4096);

    for (int t = 0; t < NTILES; t++) {
        // prefetch next B tile into the other buffer
        if (t + 1 < NTILES) {
            const int4* s4 = esrc + (size_t)(t + 1) * 1024;
            int4* d4 = sB4[(t + 1) & 1];
            #pragma unroll
            for (int i = 0; i < 4; i++) d4[tid + i * 256] = s4[tid + i * 256];
        }

        // ---- streamed zero-stores for min_encodings slice ----
        {
            const float4 z4 = make_float4(0.f, 0.f, 0.f, 0.f);
            #pragma unroll
            for (int i = 0; i < 4; i++) {
                int j = t * 1024 + i * 256 + tid;
                if (j < 32767) me4[j] = z4;
            }
            if (t == 0) {
                if (tid < 3)  out[S + tid] = 0.0f;        // unaligned head
                if (tid == 3) out[S + 131071] = 0.0f;     // tail float
            }
        }

        float acc[2][8][4];
        #pragma unroll
        for (int qb = 0; qb < 2; qb++)
            #pragma unroll
            for (int eb = 0; eb < 8; eb++)
                #pragma unroll
                for (int j = 0; j < 4; j++) acc[qb][eb][j] = 0.0f;

        const uint32_t base = aB[t & 1];
        #pragma unroll
        for (int ks = 0; ks < 4; ks++) {
            uint32_t RA[2][4];
            #pragma unroll
            for (int qb = 0; qb < 2; qb++) {
                int row = qw + qb * 16 + (l & 15);
                int blk = ks * 2 + (l >> 4);
                LDSM_X4(RA[qb], aA + row * 128 + ((blk ^ (row & 7)) << 4));
            }
            uint32_t RB[4][4];
            #pragma unroll
            for (int ebp = 0; ebp < 4; ebp++) {
                int row = ew + ebp * 16 + (l & 7) + ((l >> 4) << 3);
                int blk = ks * 2 + ((l >> 3) & 1);
                LDSM_X4(RB[ebp], base + row * 128 + ((blk ^ (row & 7)) << 4));
            }
            #pragma unroll
            for (int qb = 0; qb < 2; qb++)
                #pragma unroll
                for (int eb = 0; eb < 8; eb++)
                    mma16816(acc[qb][eb], RA[qb], &RB[eb >> 1][(eb & 1) * 2]);
        }

        // ---- epilogue: half2 max tree + gated scan ----
        #pragma unroll
        for (int qb = 0; qb < 2; qb++)
            #pragma unroll
            for (int h = 0; h < 2; h++) {
                const int slot = qb * 2 + h;
                __half2 m2 = __floats2half2_rn(acc[qb][0][h * 2],
                                               acc[qb][0][h * 2 + 1]);
                #pragma unroll
                for (int eb = 1; eb < 8; eb++)
                    m2 = __hmax2(m2, __floats2half2_rn(acc[qb][eb][h * 2],
                                                       acc[qb][eb][h * 2 + 1]));
                float mx = __half2float(__hmax(__low2half(m2), __high2half(m2)));
                mx = fmaxf(mx, __shfl_xor_sync(0xffffffffu, mx, 1));
                mx = fmaxf(mx, __shfl_xor_sync(0xffffffffu, mx, 2));
                if (mx > rm[slot]) rm[slot] = mx;
                const float thr = rm[slot] - marg[slot];
                // conservative gate (covers half rounding of mx)
                if (__any_sync(0xffffffffu, mx >= thr - 0.015f)) {
                    #pragma unroll
                    for (int eb = 0; eb < 8; eb++) {
                        #pragma unroll
                        for (int j = 0; j < 2; j++) {
                            float vv = acc[qb][eb][h * 2 + j];
                            if (vv >= thr) {
                                int sc = atomicAdd(&g_cnt[rowg[slot]], 1);
                                if (sc < CAP) {
                                    unsigned e = (unsigned)(t * NT + ew + eb * 8 +
                                                            (l & 3) * 2 + j);
                                    g_cand[(size_t)rowg[slot] * CAP + sc] =
                                        (int)((f2key(vv) << 16) | e);
                                }
                            }
                        }
                    }
                }
            }
        __syncthreads();
    }
}

// ============================================================================
// Rescore: stored-fp16-score prune, then exact fp32 dot on the survivors
// (first-index tie-break).  Overflowed rows -> exact full 4096-scan.
// ============================================================================
__global__ __launch_bounds__(256, 4)
void rescore_kernel(const float* __restrict__ z, float* __restrict__ out_idx)
{
    __shared__ float zsh[256 * 9];   // [c][hwi] pad stride 9

    const int tid = threadIdx.x;
    const int n0  = blockIdx.x * 8;
    const int b   = n0 >> 10;
    const int hw0 = n0 & 1023;
    const float* zb = z + (size_t)b * 262144 + hw0;

    #pragma unroll
    for (int w = 0; w < 8; w++) {
        int idx = tid + w * 256;
        int c = idx >> 3, hwi = idx & 7;
        zsh[c * 9 + hwi] = zb[(size_t)c * 1024 + hwi];
    }
    __syncthreads();

    const int wid = tid >> 5, lane = tid & 31;
    for (int rr = 0; rr < 4; rr++) {
        int lr  = wid * 4 + rr;
        int hwi = lr >> 2;
        int g   = lr & 3;
        int n   = n0 + hwi;
        int row = n * GR + g;
        int cnt = g_cnt[row];
        const float* zr = zsh + (g * 64) * 9 + hwi;

        float bv = -3.0e38f;
        int   be = 0x7FFFFFFF;
        if (cnt > CAP) {
            // overflow: exact scan of all 4096 embeddings (cold path)
            for (int e = lane; e < NEG; e += 32) {
                const float4* er = reinterpret_cast<const float4*>(
                    g_embn + ((size_t)(g * NEG + e)) * KD);
                float acc = 0.0f;
                #pragma unroll
                for (int kk = 0; kk < 16; kk++) {
                    float4 ev = er[kk];
                    acc = fmaf(zr[(kk * 4 + 0) * 9], ev.x, acc);
                    acc = fmaf(zr[(kk * 4 + 1) * 9], ev.y, acc);
                    acc = fmaf(zr[(kk * 4 + 2) * 9], ev.z, acc);
                    acc = fmaf(zr[(kk * 4 + 3) * 9], ev.w, acc);
                }
                if (acc > bv || (acc == bv && e < be)) { bv = acc; be = e; }
            }
        } else {
            // row norm (for prune margin)
            float s2 = 0.0f;
            #pragma unroll
            for (int c2 = 0; c2 < 2; c2++) {
                float vv = zr[(lane + c2 * 32) * 9];
                s2 += vv * vv;
            }
            #pragma unroll
            for (int m = 16; m >= 1; m >>= 1)
                s2 += __shfl_xor_sync(0xffffffffu, s2, m);

            int p0 = (lane < cnt)      ? g_cand[(size_t)row * CAP + lane]      : 0;
            int p1 = (lane + 32 < cnt) ? g_cand[(size_t)row * CAP + lane + 32] : 0;
            unsigned k0 = (unsigned)p0 >> 16;
            unsigned k1 = (unsigned)p1 >> 16;
            unsigned mk = __reduce_max_sync(0xffffffffu, max(k0, k1));
            float thr = key2f(mk) - 0.0065f * sqrtf(s2);

            #pragma unroll
            for (int hf = 0; hf < 2; hf++) {
                int p = hf ? p1 : p0;
                bool valid = hf ? (lane + 32 < cnt) : (lane < cnt);
                if (valid && key2f((unsigned)p >> 16) >= thr) {
                    int e = p & 0xFFFF;
                    const float4* er = reinterpret_cast<const float4*>(
                        g_embn + ((size_t)(g * NEG + e)) * KD);
                    float acc = 0.0f;
                    #pragma unroll
                    for (int kk = 0; kk < 16; kk++) {
                        float4 ev = er[kk];
                        acc = fmaf(zr[(kk * 4 + 0) * 9], ev.x, acc);
                        acc = fmaf(zr[(kk * 4 + 1) * 9], ev.y, acc);
                        acc = fmaf(zr[(kk * 4 + 2) * 9], ev.z, acc);
                        acc = fmaf(zr[(kk * 4 + 3) * 9], ev.w, acc);
                    }
                    if (acc > bv || (acc == bv && e < be)) { bv = acc; be = e; }
                }
            }
        }
        unsigned u = __float_as_uint(bv);
        u = ((int)u < 0) ? ~u : (u | 0x80000000u);
        unsigned m = __reduce_max_sync(0xffffffffu, u);
        unsigned bidm = (u == m) ? (unsigned)be : 0xFFFFFFFFu;
        unsigned bi = __reduce_min_sync(0xffffffffu, bidm);
        if (lane == 0) {
            g_idx[row] = (int)bi;
            out_idx[row] = (float)bi;
        }
    }
}

// ============================================================================
// quant: out[b, g*64+c, h, w] = embn[g*4096 + idx[n,g], c]
// ============================================================================
__global__ void quant_kernel(float* __restrict__ out)
{
    int o = blockIdx.x * blockDim.x + threadIdx.x;
    if (o >= 16 * 256 * 1024) return;
    int hw = o & 1023;
    int ch = (o >> 10) & 255;
    int b  = o >> 18;
    int gg = ch >> 6, c = ch & 63;
    int n  = (b << 10) + hw;
    int v  = g_idx[n * GR + gg];
    out[o] = g_embn[((size_t)((gg << 12) + v)) * KD + c];
}

// one-hot of idx[:, 3] + histogram
__global__ void scatter_kernel(float* __restrict__ out_me)
{
    int n = blockIdx.x * blockDim.x + threadIdx.x;
    if (n >= NQ) return;
    int v = g_idx[n * GR + 3];
    out_me[(size_t)n * NEG + v] = 1.0f;
    atomicAdd(&g_hist[v], 1);
}

__global__ void perp_kernel(float* __restrict__ out_p)
{
    __shared__ float red[32];
    int t = threadIdx.x;
    float s = 0.0f;
    for (int i = t; i < NEG; i += 1024) {
        float p = (float)g_hist[i] * (1.0f / 16384.0f);
        s += p * logf(p + 1e-10f);
    }
    #pragma unroll
    for (int m = 16; m >= 1; m >>= 1) s += __shfl_xor_sync(0xffffffffu, s, m);
    if ((t & 31) == 0) red[t >> 5] = s;
    __syncthreads();
    if (t < 32) {
        float x = red[t];
        #pragma unroll
        for (int m = 16; m >= 1; m >>= 1) x += __shfl_xor_sync(0xffffffffu, x, m);
        if (t == 0) out_p[0] = expf(-x);
    }
}

// ============================================================================
// Output layout (fp32, concatenated, 71,368,717 elements):
//   [0, 4194304)            quant
//   [4194304, +12)          vq_loss(4) commit_loss(4) codebook_usage(4) = zeros
//   [4194316]               perplexity
//   [4194317, +16384*4096)  min_encodings (zeroed inside vq_mma_kernel)
//   [71303181, +65536)      idx (cast to float)
// ============================================================================
extern "C" void kernel_launch(void* const* d_in, const int* in_sizes, int n_in,
                              void* d_out, int out_size)
{
    const float* z   = (const float*)d_in[0];
    const float* emb = (const float*)d_in[1];
    float* out = (float*)d_out;

    const size_t QUANT   = QUANT_SZ;                          // 4194304
    const size_t PERP    = QUANT + 12;
    const size_t ME_OFF  = ME_OFFC;                           // 4194317
    const size_t ME_SZ   = (size_t)NQ * NEG;                  // 67108864
    const size_t IDX_OFF = ME_OFF + ME_SZ;                    // 71303181

    const int SMEM = 50176;   // margins + A 16KB + 2x16KB B
    cudaFuncSetAttribute(vq_mma_kernel,
                         cudaFuncAttributeMaxDynamicSharedMemorySize, SMEM);

    // only losses + perplexity slot (13 floats); min_encodings zeroed in-kernel
    cudaMemsetAsync(out + QUANT, 0, 13 * sizeof(float));

    init_kernel<<<256, 256>>>();
    embprep_kernel<<<2048, 256>>>(emb);

    vq_mma_kernel<<<NITEMS, 256, SMEM>>>(z, out);

    rescore_kernel<<<NQ / 8, 256>>>(z, out + IDX_OFF);

    quant_kernel<<<16384, 256>>>(out);
    scatter_kernel<<<64, 256>>>(out + ME_OFF);
    perp_kernel<<<1, 1024>>>(out + PERP);
}